// round 7
// baseline (speedup 1.0000x reference)
#include <cuda_runtime.h>
#include <stdint.h>

// RVAEModel: out[b, c, g] = weight[idx[b, g], c]
//   idx:    [256, 64]  (int32 OR int64 — detected by tiny kernel)
//   weight: fp32 [1024, 1024]
//   out:    fp32 [256, 1024, 8, 8] (= [256, 1024, 64])
//
// Block = (b, quarter of c). 4 subtiles of 64 c, software-pipelined:
//   cp.async gather -> swizzled tin (double buffered, depth-2 groups)
//   LDS.128 x4 -> register 4x4 transpose -> STS.128 x4 -> tout (output layout)
//   one cp.async.bulk (TMA) store of the contiguous 16KB region per subtile
// TMA read-wait for tile h overlaps tile h+1's gather; removes all STG.128
// issue cost (12 cyc/warp-op) from the LSU path.

static constexpr int BS = 256;
static constexpr int M  = 64;    // tokens per sample (g)
static constexpr int C  = 1024;  // channels
static constexpr int NT = 4;     // subtiles per block (64 c each)

__device__ int g_idx_is64; // 1 if indices buffer is int64, 0 if int32

// Indices are in [0, 1024). If buffer is LE int64, odd 32-bit words of the
// first 64 indices are all zero; for int32 data P = (1/1024)^64 ~ 0.
// Reads 128 words — in-bounds either way.
__global__ void detect_idx_dtype(const unsigned int* __restrict__ idx_words)
{
    unsigned int acc = 0;
    #pragma unroll
    for (int i = 0; i < 64; i++) acc |= idx_words[2 * i + 1];
    g_idx_is64 = (acc == 0) ? 1 : 0;
}

__global__ __launch_bounds__(256)
void rvae_gather_transpose(const void*  __restrict__ idx_raw,
                           const float* __restrict__ w,
                           float*       __restrict__ out)
{
    const int b    = blockIdx.y;
    const int cqb  = blockIdx.x * 256;     // quarter base channel
    const int t    = threadIdx.x;          // 256 threads
    const int g_lo = t >> 4;               // this thread's g residue (0..15)
    const int c4   = t & 15;               // this thread's float4 column

    __shared__ __align__(128) float4 tin[2][M * 16]; // [buf][g*16 + (c4^(g>>2))]
    __shared__ __align__(128) float  tout[64 * M];   // [c_local*64 + g] == out layout

    // Rows this thread gathers for: g = g_lo + 16*i (same every subtile).
    int row[4];
    if (g_idx_is64) {
        #pragma unroll
        for (int i = 0; i < 4; i++)
            row[i] = (int)reinterpret_cast<const long long*>(idx_raw)[b * M + g_lo + 16 * i];
    } else {
        #pragma unroll
        for (int i = 0; i < 4; i++)
            row[i] = reinterpret_cast<const int*>(idx_raw)[b * M + g_lo + 16 * i];
    }

    // ---- gather of subtile h into tin[h&1] ----
    auto gather = [&](int h) {
        const int c0 = cqb + 64 * h;
        #pragma unroll
        for (int i = 0; i < 4; i++) {
            const int g = g_lo + 16 * i;
            const float*   src = w + (size_t)row[i] * C + c0 + (c4 << 2);
            const uint32_t dst = (uint32_t)__cvta_generic_to_shared(
                &tin[h & 1][g * 16 + (c4 ^ (g >> 2))]);
            asm volatile("cp.async.cg.shared.global [%0], [%1], 16;"
                         :: "r"(dst), "l"(src) : "memory");
        }
        asm volatile("cp.async.commit_group;" ::: "memory");
    };

    gather(0);
    gather(1);

    const int br = t & 15;  // g-quad: g = 4*br + k
    const int bc = t >> 4;  // c-quad within subtile
    const int sc = bc ^ br; // swizzled physical column of tin

    #pragma unroll
    for (int h = 0; h < NT; h++) {
        // tile h's gather complete (groups retire in commit order)
        if (h < NT - 1)
            asm volatile("cp.async.wait_group 1;" ::: "memory");
        else
            asm volatile("cp.async.wait_group 0;" ::: "memory");
        // previous TMA store must have finished READING tout before we overwrite
        if (t == 0)
            asm volatile("cp.async.bulk.wait_group.read 0;" ::: "memory");
        __syncthreads();

        const float4* ti = tin[h & 1];
        const float4 r0 = ti[(4 * br + 0) * 16 + sc];
        const float4 r1 = ti[(4 * br + 1) * 16 + sc];
        const float4 r2 = ti[(4 * br + 2) * 16 + sc];
        const float4 r3 = ti[(4 * br + 3) * 16 + sc];

        float* ot = tout + 4 * br;
        *reinterpret_cast<float4*>(ot + (4 * bc + 0) * M) = float4{r0.x, r1.x, r2.x, r3.x};
        *reinterpret_cast<float4*>(ot + (4 * bc + 1) * M) = float4{r0.y, r1.y, r2.y, r3.y};
        *reinterpret_cast<float4*>(ot + (4 * bc + 2) * M) = float4{r0.z, r1.z, r2.z, r3.z};
        *reinterpret_cast<float4*>(ot + (4 * bc + 3) * M) = float4{r0.w, r1.w, r2.w, r3.w};
        __syncthreads();

        if (t == 0) {
            asm volatile("fence.proxy.async;" ::: "memory");
            float* dst = out + (size_t)b * (C * M) + (size_t)(cqb + 64 * h) * M;
            const uint32_t src = (uint32_t)__cvta_generic_to_shared(tout);
            asm volatile(
                "cp.async.bulk.global.shared::cta.bulk_group [%0], [%1], %2;"
                :: "l"(dst), "r"(src), "r"(64 * M * 4) : "memory");
            asm volatile("cp.async.bulk.commit_group;" ::: "memory");
        }

        if (h + 2 < NT) gather(h + 2); // tin[h&1] free: all LDS done pre-barrier
    }

    // keep CTA (and its smem) alive until the final TMA read completes
    if (t == 0)
        asm volatile("cp.async.bulk.wait_group.read 0;" ::: "memory");
}

extern "C" void kernel_launch(void* const* d_in, const int* in_sizes, int n_in,
                              void* d_out, int out_size)
{
    // indices: 16384 elements; weight: 1048576 elements (fp32)
    const void*  idx;
    const float* w;
    if (in_sizes[0] == BS * M) {
        idx = d_in[0];
        w   = (const float*)d_in[1];
    } else {
        idx = d_in[1];
        w   = (const float*)d_in[0];
    }

    detect_idx_dtype<<<1, 1>>>((const unsigned int*)idx);

    dim3 grid(C / (64 * NT), BS); // (4, 256) = 1024 blocks
    rvae_gather_transpose<<<grid, 256>>>(idx, w, (float*)d_out);
}

// round 8
// speedup vs baseline: 1.1679x; 1.1679x over previous
#include <cuda_runtime.h>
#include <stdint.h>

// RVAEModel: out[b, c, g] = weight[idx[b, g], c]
//   idx:    [256, 64]  (int32 OR int64 — detected by tiny kernel)
//   weight: fp32 [1024, 1024]
//   out:    fp32 [256, 1024, 8, 8] (= [256, 1024, 64])
//
// Block = (b, 128-wide c-span) = 4 subtiles of 32 c. 128 threads.
// Per subtile: cp.async gather -> swizzled tin (double-buffered)
//   -> LDS.128 x4 -> register 4x4 transpose -> STS.128 x4 -> tout (double-
//   buffered, output layout) -> one 8KB cp.async.bulk (TMA) store.
// TMA-read waits resolve 2 subtiles later (free); stores never touch the
// LSU/STG path.

static constexpr int BS = 256;
static constexpr int M  = 64;    // tokens per sample (g)
static constexpr int C  = 1024;  // channels
static constexpr int NT = 4;     // subtiles per block
static constexpr int SC = 32;    // subtile c-width

__device__ int g_idx_is64; // 1 if indices buffer is int64, 0 if int32

// Indices are in [0, 1024). If buffer is LE int64, odd 32-bit words of the
// first 64 indices are all zero; for int32 data P = (1/1024)^64 ~ 0.
// Reads 128 words — in-bounds either way.
__global__ void detect_idx_dtype(const unsigned int* __restrict__ idx_words)
{
    unsigned int acc = 0;
    #pragma unroll
    for (int i = 0; i < 64; i++) acc |= idx_words[2 * i + 1];
    g_idx_is64 = (acc == 0) ? 1 : 0;
}

__global__ __launch_bounds__(128)
void rvae_gather_transpose(const void*  __restrict__ idx_raw,
                           const float* __restrict__ w,
                           float*       __restrict__ out)
{
    const int b   = blockIdx.y;
    const int cqb = blockIdx.x * (NT * SC); // block base channel
    const int t   = threadIdx.x;            // 128 threads

    __shared__ __align__(128) float4 tin[2][M * 8];    // 2 x 4KB, swizzled
    __shared__ __align__(128) float  tout[2][SC * M];  // 2 x 8KB, out layout

    // Gather assignment: slot = t + 128*i -> g = gb + 16*i, c4 = t&7.
    const int c4 = t & 7;
    const int gb = t >> 3; // 0..15
    int row[4];
    if (g_idx_is64) {
        #pragma unroll
        for (int i = 0; i < 4; i++)
            row[i] = (int)reinterpret_cast<const long long*>(idx_raw)[b * M + gb + 16 * i];
    } else {
        #pragma unroll
        for (int i = 0; i < 4; i++)
            row[i] = reinterpret_cast<const int*>(idx_raw)[b * M + gb + 16 * i];
    }

    auto gather = [&](int h) {
        const int c0 = cqb + SC * h;
        #pragma unroll
        for (int i = 0; i < 4; i++) {
            const int g = gb + 16 * i;
            const float*   src = w + (size_t)row[i] * C + c0 + (c4 << 2);
            const uint32_t dst = (uint32_t)__cvta_generic_to_shared(
                &tin[h & 1][g * 8 + (c4 ^ ((g >> 2) & 7))]);
            asm volatile("cp.async.cg.shared.global [%0], [%1], 16;"
                         :: "r"(dst), "l"(src) : "memory");
        }
        asm volatile("cp.async.commit_group;" ::: "memory");
    };

    gather(0);
    gather(1);

    // Transpose unit: 4g x 4c per thread.
    const int ub = t & 15;         // g-quad: g = 4*ub + k
    const int uc = t >> 4;         // c-quad: c = 4*uc + j (0..7)
    const int sc = uc ^ (ub & 7);  // swizzled tin column ((4ub+k)>>2 & 7 == ub&7)

    #pragma unroll
    for (int h = 0; h < NT; h++) {
        if (h < NT - 1)
            asm volatile("cp.async.wait_group 1;" ::: "memory");
        else
            asm volatile("cp.async.wait_group 0;" ::: "memory");
        // tout[h&1] was handed to TMA at subtile h-2; its read is long done.
        if (t == 0 && h >= 2)
            asm volatile("cp.async.bulk.wait_group.read 1;" ::: "memory");
        __syncthreads();

        const float4* ti = tin[h & 1];
        const float4 r0 = ti[(4 * ub + 0) * 8 + sc];
        const float4 r1 = ti[(4 * ub + 1) * 8 + sc];
        const float4 r2 = ti[(4 * ub + 2) * 8 + sc];
        const float4 r3 = ti[(4 * ub + 3) * 8 + sc];

        float* ot = tout[h & 1] + 4 * ub;
        *reinterpret_cast<float4*>(ot + (4 * uc + 0) * M) = float4{r0.x, r1.x, r2.x, r3.x};
        *reinterpret_cast<float4*>(ot + (4 * uc + 1) * M) = float4{r0.y, r1.y, r2.y, r3.y};
        *reinterpret_cast<float4*>(ot + (4 * uc + 2) * M) = float4{r0.z, r1.z, r2.z, r3.z};
        *reinterpret_cast<float4*>(ot + (4 * uc + 3) * M) = float4{r0.w, r1.w, r2.w, r3.w};
        __syncthreads();

        if (t == 0) {
            asm volatile("fence.proxy.async.shared::cta;" ::: "memory");
            float* dst = out + (size_t)b * (C * M) + (size_t)(cqb + SC * h) * M;
            const uint32_t src = (uint32_t)__cvta_generic_to_shared(tout[h & 1]);
            asm volatile(
                "cp.async.bulk.global.shared::cta.bulk_group [%0], [%1], %2;"
                :: "l"(dst), "r"(src), "r"(SC * M * 4) : "memory");
            asm volatile("cp.async.bulk.commit_group;" ::: "memory");
        }
        // tin[h&1] fully consumed (LDS before 2nd barrier) -> safe to refill.
        if (h + 2 < NT) gather(h + 2);
    }

    // Keep CTA (and smem) alive until the final TMA reads complete.
    if (t == 0)
        asm volatile("cp.async.bulk.wait_group.read 0;" ::: "memory");
}

extern "C" void kernel_launch(void* const* d_in, const int* in_sizes, int n_in,
                              void* d_out, int out_size)
{
    // indices: 16384 elements; weight: 1048576 elements (fp32)
    const void*  idx;
    const float* w;
    if (in_sizes[0] == BS * M) {
        idx = d_in[0];
        w   = (const float*)d_in[1];
    } else {
        idx = d_in[1];
        w   = (const float*)d_in[0];
    }

    detect_idx_dtype<<<1, 1>>>((const unsigned int*)idx);

    dim3 grid(C / (NT * SC), BS); // (8, 256) = 2048 blocks
    rvae_gather_transpose<<<grid, 128>>>(idx, w, (float*)d_out);
}